// round 13
// baseline (speedup 1.0000x reference)
#include <cuda_runtime.h>
#include <cuda_fp16.h>
#include <math.h>
#include <stdint.h>

#define B_  4
#define S_  2048
#define H_  1024
#define NH_ 16
#define HD_ 64
#define QKV_ELEMS (B_*NH_*S_*HD_)
#define XH_ELEMS  (B_*S_*H_)
#define WH_ELEMS  (H_*H_)

// Scratch: Q,K fp16 [B,NH,S,HD]; V fp16 TRANSPOSED [B,NH,HD,S]
__device__ __half g_q[QKV_ELEMS];
__device__ __half g_k[QKV_ELEMS];
__device__ __half g_vt[QKV_ELEMS];
__device__ __half g_xh[XH_ELEMS];
__device__ __half g_wh[3 * WH_ELEMS];

__device__ __forceinline__ uint32_t packh2(float lo, float hi) {
    uint32_t r;
    asm("cvt.rn.f16x2.f32 %0, %1, %2;" : "=r"(r) : "f"(hi), "f"(lo));
    return r;
}
__device__ __forceinline__ float ex2(float x) {
    float y;
    asm("ex2.approx.f32 %0, %1;" : "=f"(y) : "f"(x));
    return y;
}
__device__ __forceinline__ void mma_f16(float* c,
                                        const uint32_t* a, uint32_t b0, uint32_t b1) {
    asm volatile(
        "mma.sync.aligned.m16n8k16.row.col.f32.f16.f16.f32 "
        "{%0,%1,%2,%3}, {%4,%5,%6,%7}, {%8,%9}, {%0,%1,%2,%3};"
        : "+f"(c[0]), "+f"(c[1]), "+f"(c[2]), "+f"(c[3])
        : "r"(a[0]), "r"(a[1]), "r"(a[2]), "r"(a[3]), "r"(b0), "r"(b1));
}
__device__ __forceinline__ uint32_t smem_u32(const void* p) {
    uint32_t a;
    asm("{ .reg .u64 t; cvta.to.shared.u64 t, %1; cvt.u32.u64 %0, t; }"
        : "=r"(a) : "l"(p));
    return a;
}
__device__ __forceinline__ void cp16(uint32_t s, const void* g) {
    asm volatile("cp.async.cg.shared.global [%0], [%1], 16;"
                 :: "r"(s), "l"(g) : "memory");
}
#define CP_COMMIT() asm volatile("cp.async.commit_group;" ::: "memory")
#define CP_WAIT(n)  asm volatile("cp.async.wait_group %0;" :: "n"(n) : "memory")

// ---------------------------------------------------------------------------
// Kernel 0: fp32 -> fp16 conversion of X and the three weight matrices.
// ---------------------------------------------------------------------------
__global__ __launch_bounds__(256)
void to_half(const float* __restrict__ X,  const float* __restrict__ Wq,
             const float* __restrict__ Wk, const float* __restrict__ Wv)
{
    const int i = blockIdx.x * blockDim.x + threadIdx.x;
    const int XF4 = XH_ELEMS / 4, WF4 = WH_ELEMS / 4;
    const float* src;
    __half* dst;
    int off;
    if (i < XF4)                { src = X;  dst = g_xh;              off = i; }
    else if (i < XF4 + WF4)     { src = Wq; dst = g_wh;              off = i - XF4; }
    else if (i < XF4 + 2 * WF4) { src = Wk; dst = g_wh + WH_ELEMS;   off = i - XF4 - WF4; }
    else if (i < XF4 + 3 * WF4) { src = Wv; dst = g_wh + 2*WH_ELEMS; off = i - XF4 - 2*WF4; }
    else return;
    float4 v = ((const float4*)src)[off];
    __half2* d2 = (__half2*)dst + off * 2;
    d2[0] = __floats2half2_rn(v.x, v.y);
    d2[1] = __floats2half2_rn(v.z, v.w);
}

// ---------------------------------------------------------------------------
// Kernel 1: QKV projection — EXACT best-measured R5/R12 version (~178us).
// fp16 m16n8k16, 2-stage cp.async, K-chunk 64, scalar fragment LDS.
// ---------------------------------------------------------------------------
#define LDH 72
#define ABUF (128 * LDH)
__global__ __launch_bounds__(256)
void qkv_h(const float* __restrict__ bq, const float* __restrict__ bk,
           const float* __restrict__ bv)
{
    extern __shared__ __half sm[];    // [A0 | A1 | B0 | B1]
    __half* smA = sm;
    __half* smB = sm + 2 * ABUF;
    const uint32_t sA0 = smem_u32(smA);
    const uint32_t sB0 = smem_u32(smB);

    const int tid  = threadIdx.x;
    const int wid  = tid >> 5;
    const int lane = tid & 31;
    const int wm0  = (wid >> 2) * 64;
    const int wn0  = (wid & 3) * 32;
    const int r = lane >> 2;
    const int c = lane & 3;

    const int m0 = blockIdx.x * 128;
    const int nb = blockIdx.y;
    const int sel = nb >> 3;
    const int n0  = (nb & 7) * 128;

    const __half* __restrict__ Ag = g_xh + (size_t)m0 * 1024;
    const __half* __restrict__ Bg = g_wh + (size_t)sel * WH_ELEMS + (size_t)n0 * 1024;
    const float* __restrict__ bias = (sel == 0) ? bq : (sel == 1) ? bk : bv;

    const int lrow = tid >> 3;
    const int lc8  = tid & 7;

    {
#pragma unroll
        for (int i = 0; i < 4; i++) {
            const int row = i * 32 + lrow;
            const uint32_t so = (uint32_t)(row * LDH + lc8 * 8) * 2;
            cp16(sA0 + so, &Ag[(size_t)row * 1024 + lc8 * 8]);
            cp16(sB0 + so, &Bg[(size_t)row * 1024 + lc8 * 8]);
        }
        CP_COMMIT();
    }

    float acc[4][4][4];
#pragma unroll
    for (int mi = 0; mi < 4; mi++)
#pragma unroll
        for (int nj = 0; nj < 4; nj++)
#pragma unroll
            for (int e = 0; e < 4; e++) acc[mi][nj][e] = 0.f;

    for (int ch = 0; ch < 16; ch++) {
        const int buf = ch & 1;
        if (ch + 1 < 16) {
            const int nb2 = (ch + 1) & 1;
            const int k0 = (ch + 1) * 64;
#pragma unroll
            for (int i = 0; i < 4; i++) {
                const int row = i * 32 + lrow;
                const uint32_t so = (uint32_t)(nb2 * ABUF + row * LDH + lc8 * 8) * 2;
                cp16(sA0 + so, &Ag[(size_t)row * 1024 + k0 + lc8 * 8]);
                cp16(sB0 + so, &Bg[(size_t)row * 1024 + k0 + lc8 * 8]);
            }
            CP_COMMIT();
            CP_WAIT(1);
        } else {
            CP_WAIT(0);
        }
        __syncthreads();

        const __half* As = smA + buf * ABUF;
        const __half* Bs = smB + buf * ABUF;
#pragma unroll
        for (int kc = 0; kc < 4; kc++) {
            uint32_t af[4][4], bf[4][2];
#pragma unroll
            for (int mi = 0; mi < 4; mi++) {
                const __half* p = &As[(wm0 + mi * 16 + r) * LDH + kc * 16 + 2 * c];
                af[mi][0] = *(const uint32_t*)p;
                af[mi][1] = *(const uint32_t*)(p + 8 * LDH);
                af[mi][2] = *(const uint32_t*)(p + 8);
                af[mi][3] = *(const uint32_t*)(p + 8 * LDH + 8);
            }
#pragma unroll
            for (int nj = 0; nj < 4; nj++) {
                const __half* p = &Bs[(wn0 + nj * 8 + r) * LDH + kc * 16 + 2 * c];
                bf[nj][0] = *(const uint32_t*)p;
                bf[nj][1] = *(const uint32_t*)(p + 8);
            }
#pragma unroll
            for (int mi = 0; mi < 4; mi++)
#pragma unroll
                for (int nj = 0; nj < 4; nj++)
                    mma_f16(acc[mi][nj], af[mi], bf[nj][0], bf[nj][1]);
        }
        __syncthreads();
    }

    // Epilogue: bias + fp16 store. Q/K: [b,h][s][d]; V transposed [b,h][d][s].
#pragma unroll
    for (int nj = 0; nj < 4; nj++) {
        const int n = n0 + wn0 + nj * 8 + c * 2;
        const int h = n >> 6;
        const int d = n & 63;
        const float b0v = bias[n];
        const float b1v = bias[n + 1];
#pragma unroll
        for (int mi = 0; mi < 4; mi++) {
            const int mA = m0 + wm0 + mi * 16 + r;
            const int mB = mA + 8;
            const int bbA = mA >> 11, ssA = mA & 2047;
            const int bbB = mB >> 11, ssB = mB & 2047;
            if (sel == 2) {
                const size_t base = ((size_t)bbA * NH_ + h) * HD_;
                g_vt[(base + d)     * S_ + ssA] = __float2half(acc[mi][nj][0] + b0v);
                g_vt[(base + d + 1) * S_ + ssA] = __float2half(acc[mi][nj][1] + b1v);
                const size_t baseB = ((size_t)bbB * NH_ + h) * HD_;
                g_vt[(baseB + d)     * S_ + ssB] = __float2half(acc[mi][nj][2] + b0v);
                g_vt[(baseB + d + 1) * S_ + ssB] = __float2half(acc[mi][nj][3] + b1v);
            } else {
                __half* dst = (sel == 0) ? g_q : g_k;
                *(__half2*)&dst[(((size_t)bbA * NH_ + h) * S_ + ssA) * HD_ + d] =
                    __floats2half2_rn(acc[mi][nj][0] + b0v, acc[mi][nj][1] + b1v);
                *(__half2*)&dst[(((size_t)bbB * NH_ + h) * S_ + ssB) * HD_ + d] =
                    __floats2half2_rn(acc[mi][nj][2] + b0v, acc[mi][nj][3] + b1v);
            }
        }
    }
}

// ---------------------------------------------------------------------------
// Kernel 2: flash attention — R12 + chain-latency diet:
//   * per-lane partial lsum (row-sum reduced ONCE at the end, not per tile:
//     removes 8 SHFL/tile from the critical chain; exact identity)
//   * deferred O-rescale: skip corr + 32-reg rescale when mt <= mrun
//     (uniform branch per 4-lane row group; exact identity)
// 128 threads / 4 warps, warp = 32 q-rows, 64-key tiles, 2 CTAs/SM.
// ---------------------------------------------------------------------------
#define SCC 0.1803368801f   // 0.125 * log2(e)
__global__ __launch_bounds__(128, 2)
void flash_mma(const float* __restrict__ mask, float* __restrict__ out)
{
    __shared__ __half Qs[128 * LDH];
    __shared__ __half Ks[64 * LDH];
    __shared__ __half Vts[64 * LDH];
    __shared__ float Ms[64];

    const int qt = 15 - blockIdx.x;
    const int h  = blockIdx.y;
    const int b  = blockIdx.z;
    const int tid  = threadIdx.x;
    const int w    = tid >> 5;
    const int lane = tid & 31;
    const int r = lane >> 2;
    const int c = lane & 3;

    const int q0 = qt * 128;
    const size_t hb = ((size_t)b * NH_ + h) * S_;

    {
        const __half* qg = g_q + (hb + q0) * HD_;
#pragma unroll
        for (int i = 0; i < 8; i++) {
            const int idx = i * 128 + tid;
            const int row = idx >> 3, c8 = idx & 7;
            *(uint4*)&Qs[row * LDH + c8 * 8] = *(const uint4*)&qg[row * HD_ + c8 * 8];
        }
    }
    __syncthreads();

    uint32_t qfr[2][4][4];
#pragma unroll
    for (int mi = 0; mi < 2; mi++)
#pragma unroll
        for (int kc = 0; kc < 4; kc++) {
            const __half* p = &Qs[(w * 32 + mi * 16 + r) * LDH + kc * 16 + 2 * c];
            qfr[mi][kc][0] = *(const uint32_t*)p;
            qfr[mi][kc][1] = *(const uint32_t*)(p + 8 * LDH);
            qfr[mi][kc][2] = *(const uint32_t*)(p + 8);
            qfr[mi][kc][3] = *(const uint32_t*)(p + 8 * LDH + 8);
        }

    float of[2][8][4];
#pragma unroll
    for (int mi = 0; mi < 2; mi++)
#pragma unroll
        for (int nf = 0; nf < 8; nf++)
#pragma unroll
            for (int e = 0; e < 4; e++) of[mi][nf][e] = 0.f;
    float mrun[2][2] = {{-INFINITY, -INFINITY}, {-INFINITY, -INFINITY}};
    float lsum[2][2] = {{0.f, 0.f}, {0.f, 0.f}};   // per-lane partials

    const int qr_lo = q0 + w * 32;
    const int nkt = 2 * qt + 2;

    for (int kt = 0; kt < nkt; kt++) {
        const __half* kg = g_k + (hb + kt * 64) * HD_;
        const __half* vg = g_vt + ((size_t)b * NH_ + h) * HD_ * S_ + kt * 64;
#pragma unroll
        for (int i = 0; i < 4; i++) {
            const int idx = i * 128 + tid;
            const int row = idx >> 3, c8 = idx & 7;
            *(uint4*)&Ks[row * LDH + c8 * 8]  = *(const uint4*)&kg[row * HD_ + c8 * 8];
            *(uint4*)&Vts[row * LDH + c8 * 8] = *(const uint4*)&vg[(size_t)row * S_ + c8 * 8];
        }
        if (tid < 64) Ms[tid] = mask[(size_t)b * S_ + kt * 64 + tid] * SCC;
        __syncthreads();

        if (kt * 64 <= qr_lo + 31) {
            float sf[2][8][4];
#pragma unroll
            for (int mi = 0; mi < 2; mi++)
#pragma unroll
                for (int nf = 0; nf < 8; nf++)
#pragma unroll
                    for (int e = 0; e < 4; e++) sf[mi][nf][e] = 0.f;
#pragma unroll
            for (int kc = 0; kc < 4; kc++)
#pragma unroll
                for (int nf = 0; nf < 8; nf++) {
                    const __half* p = &Ks[(nf * 8 + r) * LDH + kc * 16 + 2 * c];
                    const uint32_t b0 = *(const uint32_t*)p;
                    const uint32_t b1 = *(const uint32_t*)(p + 8);
                    mma_f16(sf[0][nf], qfr[0][kc], b0, b1);
                    mma_f16(sf[1][nf], qfr[1][kc], b0, b1);
                }

            const bool diag = (kt * 64 + 63) > qr_lo;
            uint32_t pf[2][4][4];
#pragma unroll
            for (int mi = 0; mi < 2; mi++) {
                const int rowA = qr_lo + mi * 16 + r;
#pragma unroll
                for (int nf = 0; nf < 8; nf++) {
                    const float m0v = Ms[nf * 8 + 2 * c];
                    const float m1v = Ms[nf * 8 + 2 * c + 1];
                    sf[mi][nf][0] = fmaf(sf[mi][nf][0], SCC, m0v);
                    sf[mi][nf][1] = fmaf(sf[mi][nf][1], SCC, m1v);
                    sf[mi][nf][2] = fmaf(sf[mi][nf][2], SCC, m0v);
                    sf[mi][nf][3] = fmaf(sf[mi][nf][3], SCC, m1v);
                    if (diag) {
                        const int col0 = kt * 64 + nf * 8 + 2 * c;
                        if (col0     > rowA)     sf[mi][nf][0] = -INFINITY;
                        if (col0 + 1 > rowA)     sf[mi][nf][1] = -INFINITY;
                        if (col0     > rowA + 8) sf[mi][nf][2] = -INFINITY;
                        if (col0 + 1 > rowA + 8) sf[mi][nf][3] = -INFINITY;
                    }
                }
#pragma unroll
                for (int rr = 0; rr < 2; rr++) {
                    float mt = -INFINITY;
#pragma unroll
                    for (int nf = 0; nf < 8; nf++)
                        mt = fmaxf(mt, fmaxf(sf[mi][nf][rr * 2], sf[mi][nf][rr * 2 + 1]));
                    mt = fmaxf(mt, __shfl_xor_sync(0xffffffffu, mt, 1));
                    mt = fmaxf(mt, __shfl_xor_sync(0xffffffffu, mt, 2));
                    if (mt > mrun[mi][rr]) {            // rescale only when max moves
                        const float corr = ex2(mrun[mi][rr] - mt);   // 0 on first tile
                        mrun[mi][rr] = mt;
                        lsum[mi][rr] *= corr;
#pragma unroll
                        for (int nd = 0; nd < 8; nd++) {
                            of[mi][nd][rr * 2]     *= corr;
                            of[mi][nd][rr * 2 + 1] *= corr;
                        }
                    }
                    const float mn = mrun[mi][rr];
                    float ls = 0.f;
#pragma unroll
                    for (int nf = 0; nf < 8; nf++) {
                        const float p0 = ex2(sf[mi][nf][rr * 2]     - mn);
                        const float p1 = ex2(sf[mi][nf][rr * 2 + 1] - mn);
                        sf[mi][nf][rr * 2] = p0;
                        sf[mi][nf][rr * 2 + 1] = p1;
                        ls += p0 + p1;
                    }
                    lsum[mi][rr] += ls;                 // per-lane partial, no SHFL
                }
#pragma unroll
                for (int kc = 0; kc < 4; kc++) {
                    pf[mi][kc][0] = packh2(sf[mi][2 * kc][0],     sf[mi][2 * kc][1]);
                    pf[mi][kc][1] = packh2(sf[mi][2 * kc][2],     sf[mi][2 * kc][3]);
                    pf[mi][kc][2] = packh2(sf[mi][2 * kc + 1][0], sf[mi][2 * kc + 1][1]);
                    pf[mi][kc][3] = packh2(sf[mi][2 * kc + 1][2], sf[mi][2 * kc + 1][3]);
                }
            }

#pragma unroll
            for (int kc = 0; kc < 4; kc++)
#pragma unroll
                for (int nd = 0; nd < 8; nd++) {
                    const __half* p = &Vts[(nd * 8 + r) * LDH + kc * 16 + 2 * c];
                    const uint32_t b0 = *(const uint32_t*)p;
                    const uint32_t b1 = *(const uint32_t*)(p + 8);
                    mma_f16(of[0][nd], pf[0][kc], b0, b1);
                    mma_f16(of[1][nd], pf[1][kc], b0, b1);
                }
        }
        __syncthreads();
    }

    // ---- final cross-lane lsum reduction + normalize + store ----
#pragma unroll
    for (int mi = 0; mi < 2; mi++)
#pragma unroll
        for (int rr = 0; rr < 2; rr++) {
            float l = lsum[mi][rr];
            l += __shfl_xor_sync(0xffffffffu, l, 1);
            l += __shfl_xor_sync(0xffffffffu, l, 2);
            const float inv = 1.f / l;
            const int row = q0 + w * 32 + mi * 16 + r + rr * 8;
            float* op = out + ((size_t)b * S_ + row) * H_ + h * HD_;
#pragma unroll
            for (int nf = 0; nf < 8; nf++) {
                float2 v;
                v.x = of[mi][nf][rr * 2] * inv;
                v.y = of[mi][nf][rr * 2 + 1] * inv;
                *(float2*)&op[nf * 8 + 2 * c] = v;
            }
        }
}

// ---------------------------------------------------------------------------
extern "C" void kernel_launch(void* const* d_in, const int* in_sizes, int n_in,
                              void* d_out, int out_size)
{
    const float* hs   = (const float*)d_in[0];
    const float* mask = (const float*)d_in[1];
    const float* Wq   = (const float*)d_in[2];
    const float* bq   = (const float*)d_in[3];
    const float* Wk   = (const float*)d_in[4];
    const float* bk   = (const float*)d_in[5];
    const float* Wv   = (const float*)d_in[6];
    const float* bv   = (const float*)d_in[7];
    float* out = (float*)d_out;

    const int cvt_blocks = (XH_ELEMS / 4 + 3 * (WH_ELEMS / 4) + 255) / 256;
    to_half<<<cvt_blocks, 256>>>(hs, Wq, Wk, Wv);

    const int dynQ = 4 * ABUF * (int)sizeof(__half);   // 73,728 B
    static int attr_set = 0;
    if (!attr_set) {
        cudaFuncSetAttribute(qkv_h, cudaFuncAttributeMaxDynamicSharedMemorySize, dynQ);
        attr_set = 1;
    }
    qkv_h<<<dim3(64, 24), 256, dynQ>>>(bq, bk, bv);
    flash_mma<<<dim3(16, NH_, B_), 128>>>(mask, out);
}

// round 14
// speedup vs baseline: 1.0509x; 1.0509x over previous
#include <cuda_runtime.h>
#include <cuda_fp16.h>
#include <math.h>
#include <stdint.h>

#define B_  4
#define S_  2048
#define H_  1024
#define NH_ 16
#define HD_ 64
#define QKV_ELEMS (B_*NH_*S_*HD_)
#define XH_ELEMS  (B_*S_*H_)
#define WH_ELEMS  (H_*H_)

// Scratch: Q,K fp16 [B,NH,S,HD]; V fp16 TRANSPOSED [B,NH,HD,S]
__device__ __half g_q[QKV_ELEMS];
__device__ __half g_k[QKV_ELEMS];
__device__ __half g_vt[QKV_ELEMS];
__device__ __half g_xh[XH_ELEMS];
__device__ __half g_wh[3 * WH_ELEMS];

__device__ __forceinline__ uint32_t packh2(float lo, float hi) {
    uint32_t r;
    asm("cvt.rn.f16x2.f32 %0, %1, %2;" : "=r"(r) : "f"(hi), "f"(lo));
    return r;
}
__device__ __forceinline__ float ex2(float x) {
    float y;
    asm("ex2.approx.f32 %0, %1;" : "=f"(y) : "f"(x));
    return y;
}
__device__ __forceinline__ void mma_f16(float* c,
                                        const uint32_t* a, uint32_t b0, uint32_t b1) {
    asm volatile(
        "mma.sync.aligned.m16n8k16.row.col.f32.f16.f16.f32 "
        "{%0,%1,%2,%3}, {%4,%5,%6,%7}, {%8,%9}, {%0,%1,%2,%3};"
        : "+f"(c[0]), "+f"(c[1]), "+f"(c[2]), "+f"(c[3])
        : "r"(a[0]), "r"(a[1]), "r"(a[2]), "r"(a[3]), "r"(b0), "r"(b1));
}
__device__ __forceinline__ uint32_t smem_u32(const void* p) {
    uint32_t a;
    asm("{ .reg .u64 t; cvta.to.shared.u64 t, %1; cvt.u32.u64 %0, t; }"
        : "=r"(a) : "l"(p));
    return a;
}
__device__ __forceinline__ void cp16(uint32_t s, const void* g) {
    asm volatile("cp.async.cg.shared.global [%0], [%1], 16;"
                 :: "r"(s), "l"(g) : "memory");
}
#define CP_COMMIT() asm volatile("cp.async.commit_group;" ::: "memory")
#define CP_WAIT(n)  asm volatile("cp.async.wait_group %0;" :: "n"(n) : "memory")

// ---------------------------------------------------------------------------
// Kernel 0: fp32 -> fp16 conversion of X and the three weight matrices.
// ---------------------------------------------------------------------------
__global__ __launch_bounds__(256)
void to_half(const float* __restrict__ X,  const float* __restrict__ Wq,
             const float* __restrict__ Wk, const float* __restrict__ Wv)
{
    const int i = blockIdx.x * blockDim.x + threadIdx.x;
    const int XF4 = XH_ELEMS / 4, WF4 = WH_ELEMS / 4;
    const float* src;
    __half* dst;
    int off;
    if (i < XF4)                { src = X;  dst = g_xh;              off = i; }
    else if (i < XF4 + WF4)     { src = Wq; dst = g_wh;              off = i - XF4; }
    else if (i < XF4 + 2 * WF4) { src = Wk; dst = g_wh + WH_ELEMS;   off = i - XF4 - WF4; }
    else if (i < XF4 + 3 * WF4) { src = Wv; dst = g_wh + 2*WH_ELEMS; off = i - XF4 - 2*WF4; }
    else return;
    float4 v = ((const float4*)src)[off];
    __half2* d2 = (__half2*)dst + off * 2;
    d2[0] = __floats2half2_rn(v.x, v.y);
    d2[1] = __floats2half2_rn(v.z, v.w);
}

// ---------------------------------------------------------------------------
// Kernel 1: QKV projection — EXACT best-measured R5/R12 version (~178us).
// fp16 m16n8k16, 2-stage cp.async, K-chunk 64, scalar fragment LDS.
// ---------------------------------------------------------------------------
#define LDH 72
#define ABUF (128 * LDH)
__global__ __launch_bounds__(256)
void qkv_h(const float* __restrict__ bq, const float* __restrict__ bk,
           const float* __restrict__ bv)
{
    extern __shared__ __half sm[];    // [A0 | A1 | B0 | B1]
    __half* smA = sm;
    __half* smB = sm + 2 * ABUF;
    const uint32_t sA0 = smem_u32(smA);
    const uint32_t sB0 = smem_u32(smB);

    const int tid  = threadIdx.x;
    const int wid  = tid >> 5;
    const int lane = tid & 31;
    const int wm0  = (wid >> 2) * 64;
    const int wn0  = (wid & 3) * 32;
    const int r = lane >> 2;
    const int c = lane & 3;

    const int m0 = blockIdx.x * 128;
    const int nb = blockIdx.y;
    const int sel = nb >> 3;
    const int n0  = (nb & 7) * 128;

    const __half* __restrict__ Ag = g_xh + (size_t)m0 * 1024;
    const __half* __restrict__ Bg = g_wh + (size_t)sel * WH_ELEMS + (size_t)n0 * 1024;
    const float* __restrict__ bias = (sel == 0) ? bq : (sel == 1) ? bk : bv;

    const int lrow = tid >> 3;
    const int lc8  = tid & 7;

    {
#pragma unroll
        for (int i = 0; i < 4; i++) {
            const int row = i * 32 + lrow;
            const uint32_t so = (uint32_t)(row * LDH + lc8 * 8) * 2;
            cp16(sA0 + so, &Ag[(size_t)row * 1024 + lc8 * 8]);
            cp16(sB0 + so, &Bg[(size_t)row * 1024 + lc8 * 8]);
        }
        CP_COMMIT();
    }

    float acc[4][4][4];
#pragma unroll
    for (int mi = 0; mi < 4; mi++)
#pragma unroll
        for (int nj = 0; nj < 4; nj++)
#pragma unroll
            for (int e = 0; e < 4; e++) acc[mi][nj][e] = 0.f;

    for (int ch = 0; ch < 16; ch++) {
        const int buf = ch & 1;
        if (ch + 1 < 16) {
            const int nb2 = (ch + 1) & 1;
            const int k0 = (ch + 1) * 64;
#pragma unroll
            for (int i = 0; i < 4; i++) {
                const int row = i * 32 + lrow;
                const uint32_t so = (uint32_t)(nb2 * ABUF + row * LDH + lc8 * 8) * 2;
                cp16(sA0 + so, &Ag[(size_t)row * 1024 + k0 + lc8 * 8]);
                cp16(sB0 + so, &Bg[(size_t)row * 1024 + k0 + lc8 * 8]);
            }
            CP_COMMIT();
            CP_WAIT(1);
        } else {
            CP_WAIT(0);
        }
        __syncthreads();

        const __half* As = smA + buf * ABUF;
        const __half* Bs = smB + buf * ABUF;
#pragma unroll
        for (int kc = 0; kc < 4; kc++) {
            uint32_t af[4][4], bf[4][2];
#pragma unroll
            for (int mi = 0; mi < 4; mi++) {
                const __half* p = &As[(wm0 + mi * 16 + r) * LDH + kc * 16 + 2 * c];
                af[mi][0] = *(const uint32_t*)p;
                af[mi][1] = *(const uint32_t*)(p + 8 * LDH);
                af[mi][2] = *(const uint32_t*)(p + 8);
                af[mi][3] = *(const uint32_t*)(p + 8 * LDH + 8);
            }
#pragma unroll
            for (int nj = 0; nj < 4; nj++) {
                const __half* p = &Bs[(wn0 + nj * 8 + r) * LDH + kc * 16 + 2 * c];
                bf[nj][0] = *(const uint32_t*)p;
                bf[nj][1] = *(const uint32_t*)(p + 8);
            }
#pragma unroll
            for (int mi = 0; mi < 4; mi++)
#pragma unroll
                for (int nj = 0; nj < 4; nj++)
                    mma_f16(acc[mi][nj], af[mi], bf[nj][0], bf[nj][1]);
        }
        __syncthreads();
    }

    // Epilogue: bias + fp16 store. Q/K: [b,h][s][d]; V transposed [b,h][d][s].
#pragma unroll
    for (int nj = 0; nj < 4; nj++) {
        const int n = n0 + wn0 + nj * 8 + c * 2;
        const int h = n >> 6;
        const int d = n & 63;
        const float b0v = bias[n];
        const float b1v = bias[n + 1];
#pragma unroll
        for (int mi = 0; mi < 4; mi++) {
            const int mA = m0 + wm0 + mi * 16 + r;
            const int mB = mA + 8;
            const int bbA = mA >> 11, ssA = mA & 2047;
            const int bbB = mB >> 11, ssB = mB & 2047;
            if (sel == 2) {
                const size_t base = ((size_t)bbA * NH_ + h) * HD_;
                g_vt[(base + d)     * S_ + ssA] = __float2half(acc[mi][nj][0] + b0v);
                g_vt[(base + d + 1) * S_ + ssA] = __float2half(acc[mi][nj][1] + b1v);
                const size_t baseB = ((size_t)bbB * NH_ + h) * HD_;
                g_vt[(baseB + d)     * S_ + ssB] = __float2half(acc[mi][nj][2] + b0v);
                g_vt[(baseB + d + 1) * S_ + ssB] = __float2half(acc[mi][nj][3] + b1v);
            } else {
                __half* dst = (sel == 0) ? g_q : g_k;
                *(__half2*)&dst[(((size_t)bbA * NH_ + h) * S_ + ssA) * HD_ + d] =
                    __floats2half2_rn(acc[mi][nj][0] + b0v, acc[mi][nj][1] + b1v);
                *(__half2*)&dst[(((size_t)bbB * NH_ + h) * S_ + ssB) * HD_ + d] =
                    __floats2half2_rn(acc[mi][nj][2] + b0v, acc[mi][nj][3] + b1v);
            }
        }
    }
}

// ---------------------------------------------------------------------------
// Kernel 2: flash attention — R12 + ONE change: per-lane partial lsum
// (removes 8 SHFL/tile from the softmax chain; reduced once in the epilogue).
// Rescale stays UNCONDITIONAL exactly as in R12 (R13's branch regressed).
// 128 threads / 4 warps, warp = 32 q-rows, 64-key tiles, 2 CTAs/SM.
// ---------------------------------------------------------------------------
#define SCC 0.1803368801f   // 0.125 * log2(e)
__global__ __launch_bounds__(128, 2)
void flash_mma(const float* __restrict__ mask, float* __restrict__ out)
{
    __shared__ __half Qs[128 * LDH];
    __shared__ __half Ks[64 * LDH];
    __shared__ __half Vts[64 * LDH];
    __shared__ float Ms[64];

    const int qt = 15 - blockIdx.x;
    const int h  = blockIdx.y;
    const int b  = blockIdx.z;
    const int tid  = threadIdx.x;
    const int w    = tid >> 5;
    const int lane = tid & 31;
    const int r = lane >> 2;
    const int c = lane & 3;

    const int q0 = qt * 128;
    const size_t hb = ((size_t)b * NH_ + h) * S_;

    {
        const __half* qg = g_q + (hb + q0) * HD_;
#pragma unroll
        for (int i = 0; i < 8; i++) {
            const int idx = i * 128 + tid;
            const int row = idx >> 3, c8 = idx & 7;
            *(uint4*)&Qs[row * LDH + c8 * 8] = *(const uint4*)&qg[row * HD_ + c8 * 8];
        }
    }
    __syncthreads();

    uint32_t qfr[2][4][4];
#pragma unroll
    for (int mi = 0; mi < 2; mi++)
#pragma unroll
        for (int kc = 0; kc < 4; kc++) {
            const __half* p = &Qs[(w * 32 + mi * 16 + r) * LDH + kc * 16 + 2 * c];
            qfr[mi][kc][0] = *(const uint32_t*)p;
            qfr[mi][kc][1] = *(const uint32_t*)(p + 8 * LDH);
            qfr[mi][kc][2] = *(const uint32_t*)(p + 8);
            qfr[mi][kc][3] = *(const uint32_t*)(p + 8 * LDH + 8);
        }

    float of[2][8][4];
#pragma unroll
    for (int mi = 0; mi < 2; mi++)
#pragma unroll
        for (int nf = 0; nf < 8; nf++)
#pragma unroll
            for (int e = 0; e < 4; e++) of[mi][nf][e] = 0.f;
    float mrun[2][2] = {{-INFINITY, -INFINITY}, {-INFINITY, -INFINITY}};
    float lsum[2][2] = {{0.f, 0.f}, {0.f, 0.f}};   // per-lane partials

    const int qr_lo = q0 + w * 32;
    const int nkt = 2 * qt + 2;

    for (int kt = 0; kt < nkt; kt++) {
        const __half* kg = g_k + (hb + kt * 64) * HD_;
        const __half* vg = g_vt + ((size_t)b * NH_ + h) * HD_ * S_ + kt * 64;
#pragma unroll
        for (int i = 0; i < 4; i++) {
            const int idx = i * 128 + tid;
            const int row = idx >> 3, c8 = idx & 7;
            *(uint4*)&Ks[row * LDH + c8 * 8]  = *(const uint4*)&kg[row * HD_ + c8 * 8];
            *(uint4*)&Vts[row * LDH + c8 * 8] = *(const uint4*)&vg[(size_t)row * S_ + c8 * 8];
        }
        if (tid < 64) Ms[tid] = mask[(size_t)b * S_ + kt * 64 + tid] * SCC;
        __syncthreads();

        if (kt * 64 <= qr_lo + 31) {
            float sf[2][8][4];
#pragma unroll
            for (int mi = 0; mi < 2; mi++)
#pragma unroll
                for (int nf = 0; nf < 8; nf++)
#pragma unroll
                    for (int e = 0; e < 4; e++) sf[mi][nf][e] = 0.f;
#pragma unroll
            for (int kc = 0; kc < 4; kc++)
#pragma unroll
                for (int nf = 0; nf < 8; nf++) {
                    const __half* p = &Ks[(nf * 8 + r) * LDH + kc * 16 + 2 * c];
                    const uint32_t b0 = *(const uint32_t*)p;
                    const uint32_t b1 = *(const uint32_t*)(p + 8);
                    mma_f16(sf[0][nf], qfr[0][kc], b0, b1);
                    mma_f16(sf[1][nf], qfr[1][kc], b0, b1);
                }

            const bool diag = (kt * 64 + 63) > qr_lo;
            uint32_t pf[2][4][4];
#pragma unroll
            for (int mi = 0; mi < 2; mi++) {
                const int rowA = qr_lo + mi * 16 + r;
#pragma unroll
                for (int nf = 0; nf < 8; nf++) {
                    const float m0v = Ms[nf * 8 + 2 * c];
                    const float m1v = Ms[nf * 8 + 2 * c + 1];
                    sf[mi][nf][0] = fmaf(sf[mi][nf][0], SCC, m0v);
                    sf[mi][nf][1] = fmaf(sf[mi][nf][1], SCC, m1v);
                    sf[mi][nf][2] = fmaf(sf[mi][nf][2], SCC, m0v);
                    sf[mi][nf][3] = fmaf(sf[mi][nf][3], SCC, m1v);
                    if (diag) {
                        const int col0 = kt * 64 + nf * 8 + 2 * c;
                        if (col0     > rowA)     sf[mi][nf][0] = -INFINITY;
                        if (col0 + 1 > rowA)     sf[mi][nf][1] = -INFINITY;
                        if (col0     > rowA + 8) sf[mi][nf][2] = -INFINITY;
                        if (col0 + 1 > rowA + 8) sf[mi][nf][3] = -INFINITY;
                    }
                }
#pragma unroll
                for (int rr = 0; rr < 2; rr++) {
                    float mt = -INFINITY;
#pragma unroll
                    for (int nf = 0; nf < 8; nf++)
                        mt = fmaxf(mt, fmaxf(sf[mi][nf][rr * 2], sf[mi][nf][rr * 2 + 1]));
                    mt = fmaxf(mt, __shfl_xor_sync(0xffffffffu, mt, 1));
                    mt = fmaxf(mt, __shfl_xor_sync(0xffffffffu, mt, 2));
                    const float mn = fmaxf(mrun[mi][rr], mt);
                    const float corr = ex2(mrun[mi][rr] - mn);   // 0 on first tile
                    mrun[mi][rr] = mn;
                    float ls = 0.f;
#pragma unroll
                    for (int nf = 0; nf < 8; nf++) {
                        const float p0 = ex2(sf[mi][nf][rr * 2]     - mn);
                        const float p1 = ex2(sf[mi][nf][rr * 2 + 1] - mn);
                        sf[mi][nf][rr * 2] = p0;
                        sf[mi][nf][rr * 2 + 1] = p1;
                        ls += p0 + p1;
                    }
                    lsum[mi][rr] = lsum[mi][rr] * corr + ls;   // per-lane, no SHFL
#pragma unroll
                    for (int nf = 0; nf < 8; nf++) {
                        of[mi][nf][rr * 2]     *= corr;
                        of[mi][nf][rr * 2 + 1] *= corr;
                    }
                }
#pragma unroll
                for (int kc = 0; kc < 4; kc++) {
                    pf[mi][kc][0] = packh2(sf[mi][2 * kc][0],     sf[mi][2 * kc][1]);
                    pf[mi][kc][1] = packh2(sf[mi][2 * kc][2],     sf[mi][2 * kc][3]);
                    pf[mi][kc][2] = packh2(sf[mi][2 * kc + 1][0], sf[mi][2 * kc + 1][1]);
                    pf[mi][kc][3] = packh2(sf[mi][2 * kc + 1][2], sf[mi][2 * kc + 1][3]);
                }
            }

#pragma unroll
            for (int kc = 0; kc < 4; kc++)
#pragma unroll
                for (int nd = 0; nd < 8; nd++) {
                    const __half* p = &Vts[(nd * 8 + r) * LDH + kc * 16 + 2 * c];
                    const uint32_t b0 = *(const uint32_t*)p;
                    const uint32_t b1 = *(const uint32_t*)(p + 8);
                    mma_f16(of[0][nd], pf[0][kc], b0, b1);
                    mma_f16(of[1][nd], pf[1][kc], b0, b1);
                }
        }
        __syncthreads();
    }

    // ---- final cross-lane lsum reduction + normalize + store ----
#pragma unroll
    for (int mi = 0; mi < 2; mi++)
#pragma unroll
        for (int rr = 0; rr < 2; rr++) {
            float l = lsum[mi][rr];
            l += __shfl_xor_sync(0xffffffffu, l, 1);
            l += __shfl_xor_sync(0xffffffffu, l, 2);
            const float inv = 1.f / l;
            const int row = q0 + w * 32 + mi * 16 + r + rr * 8;
            float* op = out + ((size_t)b * S_ + row) * H_ + h * HD_;
#pragma unroll
            for (int nf = 0; nf < 8; nf++) {
                float2 v;
                v.x = of[mi][nf][rr * 2] * inv;
                v.y = of[mi][nf][rr * 2 + 1] * inv;
                *(float2*)&op[nf * 8 + 2 * c] = v;
            }
        }
}

// ---------------------------------------------------------------------------
extern "C" void kernel_launch(void* const* d_in, const int* in_sizes, int n_in,
                              void* d_out, int out_size)
{
    const float* hs   = (const float*)d_in[0];
    const float* mask = (const float*)d_in[1];
    const float* Wq   = (const float*)d_in[2];
    const float* bq   = (const float*)d_in[3];
    const float* Wk   = (const float*)d_in[4];
    const float* bk   = (const float*)d_in[5];
    const float* Wv   = (const float*)d_in[6];
    const float* bv   = (const float*)d_in[7];
    float* out = (float*)d_out;

    const int cvt_blocks = (XH_ELEMS / 4 + 3 * (WH_ELEMS / 4) + 255) / 256;
    to_half<<<cvt_blocks, 256>>>(hs, Wq, Wk, Wv);

    const int dynQ = 4 * ABUF * (int)sizeof(__half);   // 73,728 B
    static int attr_set = 0;
    if (!attr_set) {
        cudaFuncSetAttribute(qkv_h, cudaFuncAttributeMaxDynamicSharedMemorySize, dynQ);
        attr_set = 1;
    }
    qkv_h<<<dim3(64, 24), 256, dynQ>>>(bq, bk, bv);
    flash_mma<<<dim3(16, NH_, B_), 128>>>(mask, out);
}

// round 15
// speedup vs baseline: 1.0738x; 1.0217x over previous
#include <cuda_runtime.h>
#include <cuda_fp16.h>
#include <math.h>
#include <stdint.h>

#define B_  4
#define S_  2048
#define H_  1024
#define NH_ 16
#define HD_ 64
#define QKV_ELEMS (B_*NH_*S_*HD_)
#define XH_ELEMS  (B_*S_*H_)
#define WH_ELEMS  (H_*H_)

// Scratch: Q,K fp16 [B,NH,S,HD]; V fp16 TRANSPOSED [B,NH,HD,S]
__device__ __half g_q[QKV_ELEMS];
__device__ __half g_k[QKV_ELEMS];
__device__ __half g_vt[QKV_ELEMS];
__device__ __half g_xh[XH_ELEMS];
__device__ __half g_wh[3 * WH_ELEMS];

__device__ __forceinline__ uint32_t packh2(float lo, float hi) {
    uint32_t r;
    asm("cvt.rn.f16x2.f32 %0, %1, %2;" : "=r"(r) : "f"(hi), "f"(lo));
    return r;
}
__device__ __forceinline__ float ex2(float x) {
    float y;
    asm("ex2.approx.f32 %0, %1;" : "=f"(y) : "f"(x));
    return y;
}
__device__ __forceinline__ void mma_f16(float* c,
                                        const uint32_t* a, uint32_t b0, uint32_t b1) {
    asm volatile(
        "mma.sync.aligned.m16n8k16.row.col.f32.f16.f16.f32 "
        "{%0,%1,%2,%3}, {%4,%5,%6,%7}, {%8,%9}, {%0,%1,%2,%3};"
        : "+f"(c[0]), "+f"(c[1]), "+f"(c[2]), "+f"(c[3])
        : "r"(a[0]), "r"(a[1]), "r"(a[2]), "r"(a[3]), "r"(b0), "r"(b1));
}
__device__ __forceinline__ uint32_t smem_u32(const void* p) {
    uint32_t a;
    asm("{ .reg .u64 t; cvta.to.shared.u64 t, %1; cvt.u32.u64 %0, t; }"
        : "=r"(a) : "l"(p));
    return a;
}
__device__ __forceinline__ void cp16(uint32_t s, const void* g) {
    asm volatile("cp.async.cg.shared.global [%0], [%1], 16;"
                 :: "r"(s), "l"(g) : "memory");
}
#define CP_COMMIT() asm volatile("cp.async.commit_group;" ::: "memory")
#define CP_WAIT(n)  asm volatile("cp.async.wait_group %0;" :: "n"(n) : "memory")

// ---------------------------------------------------------------------------
// Kernel 0: fp32 -> fp16 conversion of X and the three weight matrices.
// ---------------------------------------------------------------------------
__global__ __launch_bounds__(256)
void to_half(const float* __restrict__ X,  const float* __restrict__ Wq,
             const float* __restrict__ Wk, const float* __restrict__ Wv)
{
    const int i = blockIdx.x * blockDim.x + threadIdx.x;
    const int XF4 = XH_ELEMS / 4, WF4 = WH_ELEMS / 4;
    const float* src;
    __half* dst;
    int off;
    if (i < XF4)                { src = X;  dst = g_xh;              off = i; }
    else if (i < XF4 + WF4)     { src = Wq; dst = g_wh;              off = i - XF4; }
    else if (i < XF4 + 2 * WF4) { src = Wk; dst = g_wh + WH_ELEMS;   off = i - XF4 - WF4; }
    else if (i < XF4 + 3 * WF4) { src = Wv; dst = g_wh + 2*WH_ELEMS; off = i - XF4 - 2*WF4; }
    else return;
    float4 v = ((const float4*)src)[off];
    __half2* d2 = (__half2*)dst + off * 2;
    d2[0] = __floats2half2_rn(v.x, v.y);
    d2[1] = __floats2half2_rn(v.z, v.w);
}

// ---------------------------------------------------------------------------
// Kernel 1: QKV projection — R5 structure + REGISTER-LEVEL FRAGMENT
// DOUBLE-BUFFERING (load kc+1 fragments while issuing kc's HMMAs; hides the
// 29-cyc LDS latency the profile showed exposed). ~118 regs, still 2 CTAs/SM.
// ---------------------------------------------------------------------------
#define LDH 72
#define ABUF (128 * LDH)
__global__ __launch_bounds__(256)
void qkv_h(const float* __restrict__ bq, const float* __restrict__ bk,
           const float* __restrict__ bv)
{
    extern __shared__ __half sm[];    // [A0 | A1 | B0 | B1]
    __half* smA = sm;
    __half* smB = sm + 2 * ABUF;
    const uint32_t sA0 = smem_u32(smA);
    const uint32_t sB0 = smem_u32(smB);

    const int tid  = threadIdx.x;
    const int wid  = tid >> 5;
    const int lane = tid & 31;
    const int wm0  = (wid >> 2) * 64;
    const int wn0  = (wid & 3) * 32;
    const int r = lane >> 2;
    const int c = lane & 3;

    const int m0 = blockIdx.x * 128;
    const int nb = blockIdx.y;
    const int sel = nb >> 3;
    const int n0  = (nb & 7) * 128;

    const __half* __restrict__ Ag = g_xh + (size_t)m0 * 1024;
    const __half* __restrict__ Bg = g_wh + (size_t)sel * WH_ELEMS + (size_t)n0 * 1024;
    const float* __restrict__ bias = (sel == 0) ? bq : (sel == 1) ? bk : bv;

    const int lrow = tid >> 3;
    const int lc8  = tid & 7;

    {
#pragma unroll
        for (int i = 0; i < 4; i++) {
            const int row = i * 32 + lrow;
            const uint32_t so = (uint32_t)(row * LDH + lc8 * 8) * 2;
            cp16(sA0 + so, &Ag[(size_t)row * 1024 + lc8 * 8]);
            cp16(sB0 + so, &Bg[(size_t)row * 1024 + lc8 * 8]);
        }
        CP_COMMIT();
    }

    float acc[4][4][4];
#pragma unroll
    for (int mi = 0; mi < 4; mi++)
#pragma unroll
        for (int nj = 0; nj < 4; nj++)
#pragma unroll
            for (int e = 0; e < 4; e++) acc[mi][nj][e] = 0.f;

    for (int ch = 0; ch < 16; ch++) {
        const int buf = ch & 1;
        if (ch + 1 < 16) {
            const int nb2 = (ch + 1) & 1;
            const int k0 = (ch + 1) * 64;
#pragma unroll
            for (int i = 0; i < 4; i++) {
                const int row = i * 32 + lrow;
                const uint32_t so = (uint32_t)(nb2 * ABUF + row * LDH + lc8 * 8) * 2;
                cp16(sA0 + so, &Ag[(size_t)row * 1024 + k0 + lc8 * 8]);
                cp16(sB0 + so, &Bg[(size_t)row * 1024 + k0 + lc8 * 8]);
            }
            CP_COMMIT();
            CP_WAIT(1);
        } else {
            CP_WAIT(0);
        }
        __syncthreads();

        const __half* As = smA + buf * ABUF;
        const __half* Bs = smB + buf * ABUF;

        // fragment double-buffer: load kc=0 into slot 0
        uint32_t af[2][4][4], bf[2][4][2];
#pragma unroll
        for (int mi = 0; mi < 4; mi++) {
            const __half* p = &As[(wm0 + mi * 16 + r) * LDH + 2 * c];
            af[0][mi][0] = *(const uint32_t*)p;
            af[0][mi][1] = *(const uint32_t*)(p + 8 * LDH);
            af[0][mi][2] = *(const uint32_t*)(p + 8);
            af[0][mi][3] = *(const uint32_t*)(p + 8 * LDH + 8);
        }
#pragma unroll
        for (int nj = 0; nj < 4; nj++) {
            const __half* p = &Bs[(wn0 + nj * 8 + r) * LDH + 2 * c];
            bf[0][nj][0] = *(const uint32_t*)p;
            bf[0][nj][1] = *(const uint32_t*)(p + 8);
        }

#pragma unroll
        for (int kc = 0; kc < 4; kc++) {
            const int cur = kc & 1;
            const int nxt = cur ^ 1;
            if (kc < 3) {   // prefetch kc+1 fragments while MMAing kc
#pragma unroll
                for (int mi = 0; mi < 4; mi++) {
                    const __half* p = &As[(wm0 + mi * 16 + r) * LDH
                                          + (kc + 1) * 16 + 2 * c];
                    af[nxt][mi][0] = *(const uint32_t*)p;
                    af[nxt][mi][1] = *(const uint32_t*)(p + 8 * LDH);
                    af[nxt][mi][2] = *(const uint32_t*)(p + 8);
                    af[nxt][mi][3] = *(const uint32_t*)(p + 8 * LDH + 8);
                }
#pragma unroll
                for (int nj = 0; nj < 4; nj++) {
                    const __half* p = &Bs[(wn0 + nj * 8 + r) * LDH
                                          + (kc + 1) * 16 + 2 * c];
                    bf[nxt][nj][0] = *(const uint32_t*)p;
                    bf[nxt][nj][1] = *(const uint32_t*)(p + 8);
                }
            }
#pragma unroll
            for (int mi = 0; mi < 4; mi++)
#pragma unroll
                for (int nj = 0; nj < 4; nj++)
                    mma_f16(acc[mi][nj], af[cur][mi], bf[cur][nj][0], bf[cur][nj][1]);
        }
        __syncthreads();
    }

    // Epilogue: bias + fp16 store. Q/K: [b,h][s][d]; V transposed [b,h][d][s].
#pragma unroll
    for (int nj = 0; nj < 4; nj++) {
        const int n = n0 + wn0 + nj * 8 + c * 2;
        const int h = n >> 6;
        const int d = n & 63;
        const float b0v = bias[n];
        const float b1v = bias[n + 1];
#pragma unroll
        for (int mi = 0; mi < 4; mi++) {
            const int mA = m0 + wm0 + mi * 16 + r;
            const int mB = mA + 8;
            const int bbA = mA >> 11, ssA = mA & 2047;
            const int bbB = mB >> 11, ssB = mB & 2047;
            if (sel == 2) {
                const size_t base = ((size_t)bbA * NH_ + h) * HD_;
                g_vt[(base + d)     * S_ + ssA] = __float2half(acc[mi][nj][0] + b0v);
                g_vt[(base + d + 1) * S_ + ssA] = __float2half(acc[mi][nj][1] + b1v);
                const size_t baseB = ((size_t)bbB * NH_ + h) * HD_;
                g_vt[(baseB + d)     * S_ + ssB] = __float2half(acc[mi][nj][2] + b0v);
                g_vt[(baseB + d + 1) * S_ + ssB] = __float2half(acc[mi][nj][3] + b1v);
            } else {
                __half* dst = (sel == 0) ? g_q : g_k;
                *(__half2*)&dst[(((size_t)bbA * NH_ + h) * S_ + ssA) * HD_ + d] =
                    __floats2half2_rn(acc[mi][nj][0] + b0v, acc[mi][nj][1] + b1v);
                *(__half2*)&dst[(((size_t)bbB * NH_ + h) * S_ + ssB) * HD_ + d] =
                    __floats2half2_rn(acc[mi][nj][2] + b0v, acc[mi][nj][3] + b1v);
            }
        }
    }
}

// ---------------------------------------------------------------------------
// Kernel 2: flash attention — EXACT R14 best (per-lane partial lsum,
// unconditional rescale, exp2-folded softmax). 128 threads, 2 CTAs/SM.
// ---------------------------------------------------------------------------
#define SCC 0.1803368801f   // 0.125 * log2(e)
__global__ __launch_bounds__(128, 2)
void flash_mma(const float* __restrict__ mask, float* __restrict__ out)
{
    __shared__ __half Qs[128 * LDH];
    __shared__ __half Ks[64 * LDH];
    __shared__ __half Vts[64 * LDH];
    __shared__ float Ms[64];

    const int qt = 15 - blockIdx.x;
    const int h  = blockIdx.y;
    const int b  = blockIdx.z;
    const int tid  = threadIdx.x;
    const int w    = tid >> 5;
    const int lane = tid & 31;
    const int r = lane >> 2;
    const int c = lane & 3;

    const int q0 = qt * 128;
    const size_t hb = ((size_t)b * NH_ + h) * S_;

    {
        const __half* qg = g_q + (hb + q0) * HD_;
#pragma unroll
        for (int i = 0; i < 8; i++) {
            const int idx = i * 128 + tid;
            const int row = idx >> 3, c8 = idx & 7;
            *(uint4*)&Qs[row * LDH + c8 * 8] = *(const uint4*)&qg[row * HD_ + c8 * 8];
        }
    }
    __syncthreads();

    uint32_t qfr[2][4][4];
#pragma unroll
    for (int mi = 0; mi < 2; mi++)
#pragma unroll
        for (int kc = 0; kc < 4; kc++) {
            const __half* p = &Qs[(w * 32 + mi * 16 + r) * LDH + kc * 16 + 2 * c];
            qfr[mi][kc][0] = *(const uint32_t*)p;
            qfr[mi][kc][1] = *(const uint32_t*)(p + 8 * LDH);
            qfr[mi][kc][2] = *(const uint32_t*)(p + 8);
            qfr[mi][kc][3] = *(const uint32_t*)(p + 8 * LDH + 8);
        }

    float of[2][8][4];
#pragma unroll
    for (int mi = 0; mi < 2; mi++)
#pragma unroll
        for (int nf = 0; nf < 8; nf++)
#pragma unroll
            for (int e = 0; e < 4; e++) of[mi][nf][e] = 0.f;
    float mrun[2][2] = {{-INFINITY, -INFINITY}, {-INFINITY, -INFINITY}};
    float lsum[2][2] = {{0.f, 0.f}, {0.f, 0.f}};   // per-lane partials

    const int qr_lo = q0 + w * 32;
    const int nkt = 2 * qt + 2;

    for (int kt = 0; kt < nkt; kt++) {
        const __half* kg = g_k + (hb + kt * 64) * HD_;
        const __half* vg = g_vt + ((size_t)b * NH_ + h) * HD_ * S_ + kt * 64;
#pragma unroll
        for (int i = 0; i < 4; i++) {
            const int idx = i * 128 + tid;
            const int row = idx >> 3, c8 = idx & 7;
            *(uint4*)&Ks[row * LDH + c8 * 8]  = *(const uint4*)&kg[row * HD_ + c8 * 8];
            *(uint4*)&Vts[row * LDH + c8 * 8] = *(const uint4*)&vg[(size_t)row * S_ + c8 * 8];
        }
        if (tid < 64) Ms[tid] = mask[(size_t)b * S_ + kt * 64 + tid] * SCC;
        __syncthreads();

        if (kt * 64 <= qr_lo + 31) {
            float sf[2][8][4];
#pragma unroll
            for (int mi = 0; mi < 2; mi++)
#pragma unroll
                for (int nf = 0; nf < 8; nf++)
#pragma unroll
                    for (int e = 0; e < 4; e++) sf[mi][nf][e] = 0.f;
#pragma unroll
            for (int kc = 0; kc < 4; kc++)
#pragma unroll
                for (int nf = 0; nf < 8; nf++) {
                    const __half* p = &Ks[(nf * 8 + r) * LDH + kc * 16 + 2 * c];
                    const uint32_t b0 = *(const uint32_t*)p;
                    const uint32_t b1 = *(const uint32_t*)(p + 8);
                    mma_f16(sf[0][nf], qfr[0][kc], b0, b1);
                    mma_f16(sf[1][nf], qfr[1][kc], b0, b1);
                }

            const bool diag = (kt * 64 + 63) > qr_lo;
            uint32_t pf[2][4][4];
#pragma unroll
            for (int mi = 0; mi < 2; mi++) {
                const int rowA = qr_lo + mi * 16 + r;
#pragma unroll
                for (int nf = 0; nf < 8; nf++) {
                    const float m0v = Ms[nf * 8 + 2 * c];
                    const float m1v = Ms[nf * 8 + 2 * c + 1];
                    sf[mi][nf][0] = fmaf(sf[mi][nf][0], SCC, m0v);
                    sf[mi][nf][1] = fmaf(sf[mi][nf][1], SCC, m1v);
                    sf[mi][nf][2] = fmaf(sf[mi][nf][2], SCC, m0v);
                    sf[mi][nf][3] = fmaf(sf[mi][nf][3], SCC, m1v);
                    if (diag) {
                        const int col0 = kt * 64 + nf * 8 + 2 * c;
                        if (col0     > rowA)     sf[mi][nf][0] = -INFINITY;
                        if (col0 + 1 > rowA)     sf[mi][nf][1] = -INFINITY;
                        if (col0     > rowA + 8) sf[mi][nf][2] = -INFINITY;
                        if (col0 + 1 > rowA + 8) sf[mi][nf][3] = -INFINITY;
                    }
                }
#pragma unroll
                for (int rr = 0; rr < 2; rr++) {
                    float mt = -INFINITY;
#pragma unroll
                    for (int nf = 0; nf < 8; nf++)
                        mt = fmaxf(mt, fmaxf(sf[mi][nf][rr * 2], sf[mi][nf][rr * 2 + 1]));
                    mt = fmaxf(mt, __shfl_xor_sync(0xffffffffu, mt, 1));
                    mt = fmaxf(mt, __shfl_xor_sync(0xffffffffu, mt, 2));
                    const float mn = fmaxf(mrun[mi][rr], mt);
                    const float corr = ex2(mrun[mi][rr] - mn);   // 0 on first tile
                    mrun[mi][rr] = mn;
                    float ls = 0.f;
#pragma unroll
                    for (int nf = 0; nf < 8; nf++) {
                        const float p0 = ex2(sf[mi][nf][rr * 2]     - mn);
                        const float p1 = ex2(sf[mi][nf][rr * 2 + 1] - mn);
                        sf[mi][nf][rr * 2] = p0;
                        sf[mi][nf][rr * 2 + 1] = p1;
                        ls += p0 + p1;
                    }
                    lsum[mi][rr] = lsum[mi][rr] * corr + ls;   // per-lane, no SHFL
#pragma unroll
                    for (int nf = 0; nf < 8; nf++) {
                        of[mi][nf][rr * 2]     *= corr;
                        of[mi][nf][rr * 2 + 1] *= corr;
                    }
                }
#pragma unroll
                for (int kc = 0; kc < 4; kc++) {
                    pf[mi][kc][0] = packh2(sf[mi][2 * kc][0],     sf[mi][2 * kc][1]);
                    pf[mi][kc][1] = packh2(sf[mi][2 * kc][2],     sf[mi][2 * kc][3]);
                    pf[mi][kc][2] = packh2(sf[mi][2 * kc + 1][0], sf[mi][2 * kc + 1][1]);
                    pf[mi][kc][3] = packh2(sf[mi][2 * kc + 1][2], sf[mi][2 * kc + 1][3]);
                }
            }

#pragma unroll
            for (int kc = 0; kc < 4; kc++)
#pragma unroll
                for (int nd = 0; nd < 8; nd++) {
                    const __half* p = &Vts[(nd * 8 + r) * LDH + kc * 16 + 2 * c];
                    const uint32_t b0 = *(const uint32_t*)p;
                    const uint32_t b1 = *(const uint32_t*)(p + 8);
                    mma_f16(of[0][nd], pf[0][kc], b0, b1);
                    mma_f16(of[1][nd], pf[1][kc], b0, b1);
                }
        }
        __syncthreads();
    }

    // ---- final cross-lane lsum reduction + normalize + store ----
#pragma unroll
    for (int mi = 0; mi < 2; mi++)
#pragma unroll
        for (int rr = 0; rr < 2; rr++) {
            float l = lsum[mi][rr];
            l += __shfl_xor_sync(0xffffffffu, l, 1);
            l += __shfl_xor_sync(0xffffffffu, l, 2);
            const float inv = 1.f / l;
            const int row = q0 + w * 32 + mi * 16 + r + rr * 8;
            float* op = out + ((size_t)b * S_ + row) * H_ + h * HD_;
#pragma unroll
            for (int nf = 0; nf < 8; nf++) {
                float2 v;
                v.x = of[mi][nf][rr * 2] * inv;
                v.y = of[mi][nf][rr * 2 + 1] * inv;
                *(float2*)&op[nf * 8 + 2 * c] = v;
            }
        }
}

// ---------------------------------------------------------------------------
extern "C" void kernel_launch(void* const* d_in, const int* in_sizes, int n_in,
                              void* d_out, int out_size)
{
    const float* hs   = (const float*)d_in[0];
    const float* mask = (const float*)d_in[1];
    const float* Wq   = (const float*)d_in[2];
    const float* bq   = (const float*)d_in[3];
    const float* Wk   = (const float*)d_in[4];
    const float* bk   = (const float*)d_in[5];
    const float* Wv   = (const float*)d_in[6];
    const float* bv   = (const float*)d_in[7];
    float* out = (float*)d_out;

    const int cvt_blocks = (XH_ELEMS / 4 + 3 * (WH_ELEMS / 4) + 255) / 256;
    to_half<<<cvt_blocks, 256>>>(hs, Wq, Wk, Wv);

    const int dynQ = 4 * ABUF * (int)sizeof(__half);   // 73,728 B
    static int attr_set = 0;
    if (!attr_set) {
        cudaFuncSetAttribute(qkv_h, cudaFuncAttributeMaxDynamicSharedMemorySize, dynQ);
        attr_set = 1;
    }
    qkv_h<<<dim3(64, 24), 256, dynQ>>>(bq, bk, bv);
    flash_mma<<<dim3(16, NH_, B_), 128>>>(mask, out);
}